// round 13
// baseline (speedup 1.0000x reference)
#include <cuda_runtime.h>
#include <cuda_fp16.h>
#include <math.h>

// VoxelHuman fused: embed + gather -> 3xFP16 (m16n8k16) MLP -> compositing.
// R8: block = 1 ray = 64 points, 256 threads (8 warps), smem ~108KB ->
//     2 blocks/SM co-resident (decoupled barriers hide latency).
// Warp tile 16x128. X/H1 pre-split f16 hi/lo. Double-buffered weight staging.

#define SU2 132            // X2 row stride (uint2)
#define BST 268            // B buffer slot stride (uint2)
#define BBUF (8*BST)       // uint2 per B buffer

#define SMEM_BYTES (64*SU2*8 + 2*BBUF*8 + 4096 + 2048 + 768 + 1024 + 1024 + 32)

__device__ __forceinline__ unsigned pack_f16x2(float hi, float lo) {
    unsigned d;
    asm("cvt.rn.f16x2.f32 %0, %1, %2;" : "=r"(d) : "f"(hi), "f"(lo));
    return d;
}

// v0 -> low half (even k), v1 -> high half (odd k)
__device__ __forceinline__ void split_pair(float v0, float v1, unsigned& hi, unsigned& lo) {
    const unsigned h = pack_f16x2(v1, v0);
    const __half2 hh = *reinterpret_cast<const __half2*>(&h);
    const float f0 = __low2float(hh);
    const float f1 = __high2float(hh);
    lo = pack_f16x2(v1 - f1, v0 - f0);
    hi = h;
}

__device__ __forceinline__ void mma_f16(float* c,
                                        unsigned a0, unsigned a1, unsigned a2, unsigned a3,
                                        unsigned b0, unsigned b1) {
    asm("mma.sync.aligned.m16n8k16.row.col.f32.f16.f16.f32 "
        "{%0,%1,%2,%3},{%4,%5,%6,%7},{%8,%9},{%0,%1,%2,%3};\n"
        : "+f"(c[0]), "+f"(c[1]), "+f"(c[2]), "+f"(c[3])
        : "r"(a0), "r"(a1), "r"(a2), "r"(a3), "r"(b0), "r"(b1));
}

// Accurate fp32 sincos (Cody-Waite) — immune to --use_fast_math MUFU reduction.
__device__ __forceinline__ void sincos_acc(float x, float* sp, float* cp) {
    const float j = rintf(x * 0.636619772367581343f);
    const int   q = (int)j;
    float r = fmaf(j, -1.57079637050628662109375f, x);
    r = fmaf(j,  4.37113882867379290e-08f, r);
    r = fmaf(j,  1.71512451000590810e-15f, r);
    const float r2 = r * r;
    float sr = -1.9812813e-4f;
    sr = fmaf(sr, r2,  8.3333226e-3f);
    sr = fmaf(sr, r2, -1.6666667e-1f);
    sr = fmaf(sr * r2, r, r);
    float cr =  2.4372668e-5f;
    cr = fmaf(cr, r2, -1.3887316e-3f);
    cr = fmaf(cr, r2,  4.1666646e-2f);
    cr = fmaf(cr, r2, -5.0000000e-1f);
    cr = fmaf(cr, r2,  1.0f);
    float ss = (q & 1) ? cr : sr;
    float cc = (q & 1) ? sr : cr;
    if (q & 2) ss = -ss;
    if (((q & 2) != 0) != ((q & 1) != 0)) cc = -cc;
    *sp = ss; *cp = cc;
}

__global__ void __launch_bounds__(256, 2)
vh_kernel(const float* __restrict__ rays_o, const float* __restrict__ rays_d,
          const float* __restrict__ uv_feat, const float* __restrict__ transforms,
          const float* __restrict__ w0, const float* __restrict__ b0,
          const float* __restrict__ w1, const float* __restrict__ b1,
          const float* __restrict__ w_out, const float* __restrict__ b_out,
          const int* __restrict__ uv_idx, const int* __restrict__ vox_idx,
          float* __restrict__ out)
{
    extern __shared__ char smraw[];
    uint2* X2    = (uint2*)smraw;               // 64 x SU2 {hi,lo} f16x2 pairs
    uint2* Bb    = X2 + 64 * SU2;               // [2][8][BST] {hi,lo}
    float* WoutS = (float*)(Bb + 2 * BBUF);     // 1024
    float* rawS  = WoutS + 1024;                // 2 x 64 x 4
    float* TfS   = rawS + 512;                  // 192
    float* b0S   = TfS + 192;                   // 256
    float* b1S   = b0S + 256;                   // 256
    float* boS   = b1S + 256;                   // 4 (pad 8)

    const int tid  = threadIdx.x;
    const int lane = tid & 31;
    const int warp = tid >> 5;           // 0..7
    const int gid  = lane >> 2;
    const int tig  = lane & 3;
    const int mrow = (warp >> 1) * 16;   // 16-row group
    const int nh   = (warp & 1) * 128;   // 128-col half

    const int kp   = tid >> 5;           // weight k-pair 0..7
    const int c8   = tid & 31;           // weight col-quad (and +32)

    // stage small constants
    for (int i = tid; i < 192;  i += 256) TfS[i]   = transforms[i];
    for (int i = tid; i < 1024; i += 256) WoutS[i] = w_out[i];
    b0S[tid] = b0[tid];
    b1S[tid] = b1[tid];
    if (tid < 4) boS[tid] = b_out[tid];
    __syncthreads();

    const int g    = blockIdx.x;         // ray index
    const int base = g * 64;             // flat point base

    // hoisted weight cursors (two column quads per thread)
    const float4* w0a = (const float4*)w0 + c8;
    const float4* w0b = w0a + 32;
    const float4* w1a = (const float4*)w1 + c8;
    const float4* w1b = w1a + 32;
    // layer-0 smem k layout: [0..62]=w0 rows 0..62, 63=zero, [64..211]=w0 rows 63..210
    auto ldw0 = [](const float4* cur, int k) -> float4 {
        if (k < 63)  return cur[(size_t)k * 64];
        if (k >= 64 && k < 212) return cur[(size_t)(k - 1) * 64];
        return make_float4(0.f, 0.f, 0.f, 0.f);
    };

    float4 qa0, qa1, qb0, qb1;   // prefetched next chunk (rows 2kp, 2kp+1; quads c8, c8+32)
    qa0 = ldw0(w0a, 2 * kp);  qa1 = ldw0(w0a, 2 * kp + 1);
    qb0 = ldw0(w0b, 2 * kp);  qb1 = ldw0(w0b, 2 * kp + 1);

    // ---------------- Phase 1: build X (pre-split hi/lo pairs) ----------------
    if (tid < 64) {
        const int p = tid;                 // sample index 0..63
        const float z = 0.5f + (float)p * (1.5f / 64.0f);
        const float px = rays_o[g*3+0] + rays_d[g*3+0] * z;
        const float py = rays_o[g*3+1] + rays_d[g*3+1] * z;
        const float pz = rays_o[g*3+2] + rays_d[g*3+2] * z;
        const int vox = vox_idx[base + p];
        const float* T = TfS + vox * 12;
        float xv[64];
        xv[0] = T[0]*px + T[1]*py + T[2]*pz  + T[3];
        xv[1] = T[4]*px + T[5]*py + T[6]*pz  + T[7];
        xv[2] = T[8]*px + T[9]*py + T[10]*pz + T[11];
        float f = 1.0f;
        #pragma unroll
        for (int k = 0; k < 10; ++k) {
            float s, c;
            sincos_acc(xv[0] * f, &s, &c); xv[3+6*k+0] = s; xv[3+6*k+3] = c;
            sincos_acc(xv[1] * f, &s, &c); xv[3+6*k+1] = s; xv[3+6*k+4] = c;
            sincos_acc(xv[2] * f, &s, &c); xv[3+6*k+2] = s; xv[3+6*k+5] = c;
            f *= 2.0f;
        }
        xv[63] = 0.0f;
        uint2* xr = X2 + p * SU2;
        #pragma unroll
        for (int q = 0; q < 32; ++q) {
            unsigned h, l;
            split_pair(xv[2*q], xv[2*q+1], h, l);
            xr[q] = make_uint2(h, l);
        }
        #pragma unroll
        for (int q = 106; q < 112; ++q) xr[q] = make_uint2(0u, 0u);
    } else {
        // 192 threads gather uv_feat (148 ch): 3 threads per point
        const int t3  = tid - 64;
        const int p   = t3 & 63;
        const int sub = t3 >> 6;        // 0..2
        const int bi  = g >> 13;        // batch index (8192 rays per batch)
        const int uvi = uv_idx[base + p];
        const float4* src =
            (const float4*)(uv_feat + ((size_t)bi * 65536 + (size_t)uvi) * 148);
        uint2* xr = X2 + p * SU2;
        for (int q = sub; q < 37; q += 3) {
            const float4 v = src[q];
            unsigned h0, l0, h1, l1;
            split_pair(v.x, v.y, h0, l0);
            split_pair(v.z, v.w, h1, l1);
            *(uint4*)(xr + 32 + 2 * q) = make_uint4(h0, l0, h1, l1);
        }
    }

    // stage chunk 0 into buf 0
    uint4* stgA = (uint4*)(Bb + kp * BST + c8 * 4);
    uint4* stgB = (uint4*)(Bb + kp * BST + (c8 + 32) * 4);
    {
        unsigned h0,l0,h1,l1,h2,l2,h3,l3;
        split_pair(qa0.x, qa1.x, h0, l0); split_pair(qa0.y, qa1.y, h1, l1);
        split_pair(qa0.z, qa1.z, h2, l2); split_pair(qa0.w, qa1.w, h3, l3);
        stgA[0] = make_uint4(h0, l0, h1, l1);
        stgA[1] = make_uint4(h2, l2, h3, l3);
        split_pair(qb0.x, qb1.x, h0, l0); split_pair(qb0.y, qb1.y, h1, l1);
        split_pair(qb0.z, qb1.z, h2, l2); split_pair(qb0.w, qb1.w, h3, l3);
        stgB[0] = make_uint4(h0, l0, h1, l1);
        stgB[1] = make_uint4(h2, l2, h3, l3);
    }
    // prefetch chunk 1
    qa0 = ldw0(w0a, 16 + 2 * kp);  qa1 = ldw0(w0a, 16 + 2 * kp + 1);
    qb0 = ldw0(w0b, 16 + 2 * kp);  qb1 = ldw0(w0b, 16 + 2 * kp + 1);

    float acc[64];
    #pragma unroll
    for (int i = 0; i < 64; ++i) acc[i] = 0.0f;

    // hoisted A-row cursors (advance +8 per chunk, reset at layer switch)
    const uint2* rA0base = X2 + (mrow + gid) * SU2 + tig;
    const uint2* rA0 = rA0base;
    const uint2* rA1 = rA0base + 8 * SU2;
    // hoisted B-read cursors
    const uint2* bB0 = Bb + tig * BST + nh + gid;
    const uint2* bB1 = Bb + (tig + 4) * BST + nh + gid;

    __syncthreads();

    // ================= Unified chunk loop: 14 (layer0) + 16 (layer1) =================
    #pragma unroll 2
    for (int c = 0; c < 30; ++c) {
        // stage prefetched chunk c+1 into the other buffer
        if (c < 29) {
            unsigned h0,l0,h1,l1,h2,l2,h3,l3;
            uint4* dA = stgA + ((c + 1) & 1) * (BBUF / 2);
            uint4* dB = stgB + ((c + 1) & 1) * (BBUF / 2);
            split_pair(qa0.x, qa1.x, h0, l0); split_pair(qa0.y, qa1.y, h1, l1);
            split_pair(qa0.z, qa1.z, h2, l2); split_pair(qa0.w, qa1.w, h3, l3);
            dA[0] = make_uint4(h0, l0, h1, l1);
            dA[1] = make_uint4(h2, l2, h3, l3);
            split_pair(qb0.x, qb1.x, h0, l0); split_pair(qb0.y, qb1.y, h1, l1);
            split_pair(qb0.z, qb1.z, h2, l2); split_pair(qb0.w, qb1.w, h3, l3);
            dB[0] = make_uint4(h0, l0, h1, l1);
            dB[1] = make_uint4(h2, l2, h3, l3);
        }
        // prefetch chunk c+2
        if (c < 28) {
            const int nc = c + 2;
            if (nc < 14) {
                const int k0 = nc * 16 + 2 * kp;
                qa0 = ldw0(w0a, k0);  qa1 = ldw0(w0a, k0 + 1);
                qb0 = ldw0(w0b, k0);  qb1 = ldw0(w0b, k0 + 1);
            } else {
                const size_t k0 = (size_t)((nc - 14) * 16 + 2 * kp) * 64;
                qa0 = w1a[k0];  qa1 = w1a[k0 + 64];
                qb0 = w1b[k0];  qb1 = w1b[k0 + 64];
            }
        }
        // MMA chunk c (warp tile 16 x 128)
        {
            const uint2* Bc0 = bB0 + (c & 1) * BBUF;
            const uint2* Bc1 = bB1 + (c & 1) * BBUF;
            uint2 A0[4];
            A0[0] = rA0[0]; A0[1] = rA1[0]; A0[2] = rA0[4]; A0[3] = rA1[4];
            #pragma unroll
            for (int j = 0; j < 16; ++j) {
                const uint2 p0 = Bc0[j * 8];
                const uint2 p1 = Bc1[j * 8];
                float* ac = &acc[j * 4];
                mma_f16(ac, A0[0].x, A0[1].x, A0[2].x, A0[3].x, p0.x, p1.x);
                mma_f16(ac, A0[0].x, A0[1].x, A0[2].x, A0[3].x, p0.y, p1.y);
                mma_f16(ac, A0[0].y, A0[1].y, A0[2].y, A0[3].y, p0.x, p1.x);
            }
        }
        __syncthreads();
        if (c == 13) {
            // H1 writeback: relu(+b0), split to hi/lo, own rows/cols only
            const int r0 = mrow + gid;
            #pragma unroll
            for (int j = 0; j < 16; ++j) {
                float* ac = &acc[j * 4];
                const int gc = nh + j * 8 + tig * 2;
                const int pi = gc >> 1;
                const float h00 = fmaxf(ac[0] + b0S[gc],   0.0f);
                const float h01 = fmaxf(ac[1] + b0S[gc+1], 0.0f);
                const float h10 = fmaxf(ac[2] + b0S[gc],   0.0f);
                const float h11 = fmaxf(ac[3] + b0S[gc+1], 0.0f);
                unsigned h, l;
                split_pair(h00, h01, h, l); X2[r0 * SU2 + pi]       = make_uint2(h, l);
                split_pair(h10, h11, h, l); X2[(r0 + 8) * SU2 + pi] = make_uint2(h, l);
                ac[0] = 0.0f; ac[1] = 0.0f; ac[2] = 0.0f; ac[3] = 0.0f;
            }
            __syncthreads();
            rA0 = rA0base;
            rA1 = rA0base + 8 * SU2;
        } else {
            rA0 += 8; rA1 += 8;
        }
    }

    // ========== Layer 2 (fp32): relu(+b1) then @ w_out[256,4], half partials ==========
    {
        float pA[4] = {0,0,0,0}, pB[4] = {0,0,0,0};
        #pragma unroll
        for (int j = 0; j < 16; ++j) {
            float* ac = &acc[j * 4];
            const int gc = nh + j * 8 + tig * 2;
            const float h00 = fmaxf(ac[0] + b1S[gc],   0.0f);
            const float h01 = fmaxf(ac[1] + b1S[gc+1], 0.0f);
            const float h10 = fmaxf(ac[2] + b1S[gc],   0.0f);
            const float h11 = fmaxf(ac[3] + b1S[gc+1], 0.0f);
            #pragma unroll
            for (int o = 0; o < 4; ++o) {
                const float wv0 = WoutS[gc * 4 + o];
                const float wv1 = WoutS[(gc + 1) * 4 + o];
                pA[o] += h00 * wv0 + h01 * wv1;
                pB[o] += h10 * wv0 + h11 * wv1;
            }
        }
        #pragma unroll
        for (int m = 1; m <= 2; m <<= 1) {
            #pragma unroll
            for (int o = 0; o < 4; ++o) {
                pA[o] += __shfl_xor_sync(0xffffffffu, pA[o], m);
                pB[o] += __shfl_xor_sync(0xffffffffu, pB[o], m);
            }
        }
        if (tig == 0) {
            float* rb = rawS + (warp & 1) * 256;
            #pragma unroll
            for (int o = 0; o < 4; ++o) {
                rb[(mrow + gid)     * 4 + o] = pA[o];
                rb[(mrow + gid + 8) * 4 + o] = pB[o];
            }
        }
    }
    __syncthreads();

    // ---------------- Compositing: one thread (1 ray/block) ----------------
    if (tid == 0) {
        const float dx = rays_d[g*3], dy = rays_d[g*3+1], dz = rays_d[g*3+2];
        const float nd = sqrtf(dx*dx + dy*dy + dz*dz);
        float trans = 1.0f, r0 = 0.0f, r1 = 0.0f, r2 = 0.0f;
        const float ddist = 1.5f / 64.0f;
        for (int n = 0; n < 64; ++n) {
            float raw[4];
            #pragma unroll
            for (int o = 0; o < 4; ++o)
                raw[o] = rawS[n*4+o] + rawS[256 + n*4+o] + boS[o];
            const float sigma = fmaxf(raw[3], 0.0f);
            const float dist  = (n == 63) ? 1e10f : ddist;
            const float alpha = 1.0f - expf(-sigma * dist * nd);
            const float wgt   = alpha * trans;
            trans = trans * (1.0f - alpha + 1e-10f);
            r0 += wgt / (1.0f + expf(-raw[0]));
            r1 += wgt / (1.0f + expf(-raw[1]));
            r2 += wgt / (1.0f + expf(-raw[2]));
        }
        out[g*3+0] = r0; out[g*3+1] = r1; out[g*3+2] = r2;
    }
}

extern "C" void kernel_launch(void* const* d_in, const int* in_sizes, int n_in,
                              void* d_out, int out_size)
{
    const float* rays_o     = (const float*)d_in[0];
    const float* rays_d     = (const float*)d_in[1];
    const float* uv_feat    = (const float*)d_in[2];
    const float* transforms = (const float*)d_in[3];
    const float* w0         = (const float*)d_in[4];
    const float* b0         = (const float*)d_in[5];
    const float* w1         = (const float*)d_in[6];
    const float* b1         = (const float*)d_in[7];
    const float* w_out      = (const float*)d_in[8];
    const float* b_out      = (const float*)d_in[9];
    const int*   uv_idx     = (const int*)d_in[10];
    const int*   vox_idx    = (const int*)d_in[11];
    float* out = (float*)d_out;

    cudaFuncSetAttribute(vh_kernel, cudaFuncAttributeMaxDynamicSharedMemorySize, SMEM_BYTES);

    vh_kernel<<<16384, 256, SMEM_BYTES>>>(rays_o, rays_d, uv_feat, transforms,
                                          w0, b0, w1, b1, w_out, b_out,
                                          uv_idx, vox_idx, out);
}

// round 14
// speedup vs baseline: 1.0003x; 1.0003x over previous
#include <cuda_runtime.h>
#include <cuda_fp16.h>
#include <math.h>

// VoxelHuman fused: embed + gather -> 3xFP16 (m16n8k16) MLP -> compositing.
// R8: block = 1 ray = 64 points, 256 threads (8 warps), smem ~108KB ->
//     2 blocks/SM co-resident (decoupled barriers hide latency).
// Warp tile 16x128. X/H1 pre-split f16 hi/lo. Double-buffered weight staging.

#define SU2 132            // X2 row stride (uint2)
#define BST 268            // B buffer slot stride (uint2)
#define BBUF (8*BST)       // uint2 per B buffer

#define SMEM_BYTES (64*SU2*8 + 2*BBUF*8 + 4096 + 2048 + 768 + 1024 + 1024 + 32)

__device__ __forceinline__ unsigned pack_f16x2(float hi, float lo) {
    unsigned d;
    asm("cvt.rn.f16x2.f32 %0, %1, %2;" : "=r"(d) : "f"(hi), "f"(lo));
    return d;
}

// v0 -> low half (even k), v1 -> high half (odd k)
__device__ __forceinline__ void split_pair(float v0, float v1, unsigned& hi, unsigned& lo) {
    const unsigned h = pack_f16x2(v1, v0);
    const __half2 hh = *reinterpret_cast<const __half2*>(&h);
    const float f0 = __low2float(hh);
    const float f1 = __high2float(hh);
    lo = pack_f16x2(v1 - f1, v0 - f0);
    hi = h;
}

__device__ __forceinline__ void mma_f16(float* c,
                                        unsigned a0, unsigned a1, unsigned a2, unsigned a3,
                                        unsigned b0, unsigned b1) {
    asm("mma.sync.aligned.m16n8k16.row.col.f32.f16.f16.f32 "
        "{%0,%1,%2,%3},{%4,%5,%6,%7},{%8,%9},{%0,%1,%2,%3};\n"
        : "+f"(c[0]), "+f"(c[1]), "+f"(c[2]), "+f"(c[3])
        : "r"(a0), "r"(a1), "r"(a2), "r"(a3), "r"(b0), "r"(b1));
}

// Accurate fp32 sincos (Cody-Waite) — immune to --use_fast_math MUFU reduction.
__device__ __forceinline__ void sincos_acc(float x, float* sp, float* cp) {
    const float j = rintf(x * 0.636619772367581343f);
    const int   q = (int)j;
    float r = fmaf(j, -1.57079637050628662109375f, x);
    r = fmaf(j,  4.37113882867379290e-08f, r);
    r = fmaf(j,  1.71512451000590810e-15f, r);
    const float r2 = r * r;
    float sr = -1.9812813e-4f;
    sr = fmaf(sr, r2,  8.3333226e-3f);
    sr = fmaf(sr, r2, -1.6666667e-1f);
    sr = fmaf(sr * r2, r, r);
    float cr =  2.4372668e-5f;
    cr = fmaf(cr, r2, -1.3887316e-3f);
    cr = fmaf(cr, r2,  4.1666646e-2f);
    cr = fmaf(cr, r2, -5.0000000e-1f);
    cr = fmaf(cr, r2,  1.0f);
    float ss = (q & 1) ? cr : sr;
    float cc = (q & 1) ? sr : cr;
    if (q & 2) ss = -ss;
    if (((q & 2) != 0) != ((q & 1) != 0)) cc = -cc;
    *sp = ss; *cp = cc;
}

__global__ void __launch_bounds__(256, 2)
vh_kernel(const float* __restrict__ rays_o, const float* __restrict__ rays_d,
          const float* __restrict__ uv_feat, const float* __restrict__ transforms,
          const float* __restrict__ w0, const float* __restrict__ b0,
          const float* __restrict__ w1, const float* __restrict__ b1,
          const float* __restrict__ w_out, const float* __restrict__ b_out,
          const int* __restrict__ uv_idx, const int* __restrict__ vox_idx,
          float* __restrict__ out)
{
    extern __shared__ char smraw[];
    uint2* X2    = (uint2*)smraw;               // 64 x SU2 {hi,lo} f16x2 pairs
    uint2* Bb    = X2 + 64 * SU2;               // [2][8][BST] {hi,lo}
    float* WoutS = (float*)(Bb + 2 * BBUF);     // 1024
    float* rawS  = WoutS + 1024;                // 2 x 64 x 4
    float* TfS   = rawS + 512;                  // 192
    float* b0S   = TfS + 192;                   // 256
    float* b1S   = b0S + 256;                   // 256
    float* boS   = b1S + 256;                   // 4 (pad 8)

    const int tid  = threadIdx.x;
    const int lane = tid & 31;
    const int warp = tid >> 5;           // 0..7
    const int gid  = lane >> 2;
    const int tig  = lane & 3;
    const int mrow = (warp >> 1) * 16;   // 16-row group
    const int nh   = (warp & 1) * 128;   // 128-col half

    const int kp   = tid >> 5;           // weight k-pair 0..7
    const int c8   = tid & 31;           // weight col-quad (and +32)

    // stage small constants
    for (int i = tid; i < 192;  i += 256) TfS[i]   = transforms[i];
    for (int i = tid; i < 1024; i += 256) WoutS[i] = w_out[i];
    b0S[tid] = b0[tid];
    b1S[tid] = b1[tid];
    if (tid < 4) boS[tid] = b_out[tid];
    __syncthreads();

    const int g    = blockIdx.x;         // ray index
    const int base = g * 64;             // flat point base

    // hoisted weight cursors (two column quads per thread)
    const float4* w0a = (const float4*)w0 + c8;
    const float4* w0b = w0a + 32;
    const float4* w1a = (const float4*)w1 + c8;
    const float4* w1b = w1a + 32;
    // layer-0 smem k layout: [0..62]=w0 rows 0..62, 63=zero, [64..211]=w0 rows 63..210
    auto ldw0 = [](const float4* cur, int k) -> float4 {
        if (k < 63)  return cur[(size_t)k * 64];
        if (k >= 64 && k < 212) return cur[(size_t)(k - 1) * 64];
        return make_float4(0.f, 0.f, 0.f, 0.f);
    };

    float4 qa0, qa1, qb0, qb1;   // prefetched next chunk (rows 2kp, 2kp+1; quads c8, c8+32)
    qa0 = ldw0(w0a, 2 * kp);  qa1 = ldw0(w0a, 2 * kp + 1);
    qb0 = ldw0(w0b, 2 * kp);  qb1 = ldw0(w0b, 2 * kp + 1);

    // ---------------- Phase 1: build X (pre-split hi/lo pairs) ----------------
    if (tid < 64) {
        const int p = tid;                 // sample index 0..63
        const float z = 0.5f + (float)p * (1.5f / 64.0f);
        const float px = rays_o[g*3+0] + rays_d[g*3+0] * z;
        const float py = rays_o[g*3+1] + rays_d[g*3+1] * z;
        const float pz = rays_o[g*3+2] + rays_d[g*3+2] * z;
        const int vox = vox_idx[base + p];
        const float* T = TfS + vox * 12;
        float xv[64];
        xv[0] = T[0]*px + T[1]*py + T[2]*pz  + T[3];
        xv[1] = T[4]*px + T[5]*py + T[6]*pz  + T[7];
        xv[2] = T[8]*px + T[9]*py + T[10]*pz + T[11];
        float f = 1.0f;
        #pragma unroll
        for (int k = 0; k < 10; ++k) {
            float s, c;
            sincos_acc(xv[0] * f, &s, &c); xv[3+6*k+0] = s; xv[3+6*k+3] = c;
            sincos_acc(xv[1] * f, &s, &c); xv[3+6*k+1] = s; xv[3+6*k+4] = c;
            sincos_acc(xv[2] * f, &s, &c); xv[3+6*k+2] = s; xv[3+6*k+5] = c;
            f *= 2.0f;
        }
        xv[63] = 0.0f;
        uint2* xr = X2 + p * SU2;
        #pragma unroll
        for (int q = 0; q < 32; ++q) {
            unsigned h, l;
            split_pair(xv[2*q], xv[2*q+1], h, l);
            xr[q] = make_uint2(h, l);
        }
        #pragma unroll
        for (int q = 106; q < 112; ++q) xr[q] = make_uint2(0u, 0u);
    } else {
        // 192 threads gather uv_feat (148 ch): 3 threads per point
        const int t3  = tid - 64;
        const int p   = t3 & 63;
        const int sub = t3 >> 6;        // 0..2
        const int bi  = g >> 13;        // batch index (8192 rays per batch)
        const int uvi = uv_idx[base + p];
        const float4* src =
            (const float4*)(uv_feat + ((size_t)bi * 65536 + (size_t)uvi) * 148);
        uint2* xr = X2 + p * SU2;
        for (int q = sub; q < 37; q += 3) {
            const float4 v = src[q];
            unsigned h0, l0, h1, l1;
            split_pair(v.x, v.y, h0, l0);
            split_pair(v.z, v.w, h1, l1);
            *(uint4*)(xr + 32 + 2 * q) = make_uint4(h0, l0, h1, l1);
        }
    }

    // stage chunk 0 into buf 0
    uint4* stgA = (uint4*)(Bb + kp * BST + c8 * 4);
    uint4* stgB = (uint4*)(Bb + kp * BST + (c8 + 32) * 4);
    {
        unsigned h0,l0,h1,l1,h2,l2,h3,l3;
        split_pair(qa0.x, qa1.x, h0, l0); split_pair(qa0.y, qa1.y, h1, l1);
        split_pair(qa0.z, qa1.z, h2, l2); split_pair(qa0.w, qa1.w, h3, l3);
        stgA[0] = make_uint4(h0, l0, h1, l1);
        stgA[1] = make_uint4(h2, l2, h3, l3);
        split_pair(qb0.x, qb1.x, h0, l0); split_pair(qb0.y, qb1.y, h1, l1);
        split_pair(qb0.z, qb1.z, h2, l2); split_pair(qb0.w, qb1.w, h3, l3);
        stgB[0] = make_uint4(h0, l0, h1, l1);
        stgB[1] = make_uint4(h2, l2, h3, l3);
    }
    // prefetch chunk 1
    qa0 = ldw0(w0a, 16 + 2 * kp);  qa1 = ldw0(w0a, 16 + 2 * kp + 1);
    qb0 = ldw0(w0b, 16 + 2 * kp);  qb1 = ldw0(w0b, 16 + 2 * kp + 1);

    float acc[64];
    #pragma unroll
    for (int i = 0; i < 64; ++i) acc[i] = 0.0f;

    // hoisted A-row cursors (advance +8 per chunk, reset at layer switch)
    const uint2* rA0base = X2 + (mrow + gid) * SU2 + tig;
    const uint2* rA0 = rA0base;
    const uint2* rA1 = rA0base + 8 * SU2;
    // hoisted B-read cursors
    const uint2* bB0 = Bb + tig * BST + nh + gid;
    const uint2* bB1 = Bb + (tig + 4) * BST + nh + gid;

    __syncthreads();

    // ================= Unified chunk loop: 14 (layer0) + 16 (layer1) =================
    #pragma unroll 2
    for (int c = 0; c < 30; ++c) {
        // stage prefetched chunk c+1 into the other buffer
        if (c < 29) {
            unsigned h0,l0,h1,l1,h2,l2,h3,l3;
            uint4* dA = stgA + ((c + 1) & 1) * (BBUF / 2);
            uint4* dB = stgB + ((c + 1) & 1) * (BBUF / 2);
            split_pair(qa0.x, qa1.x, h0, l0); split_pair(qa0.y, qa1.y, h1, l1);
            split_pair(qa0.z, qa1.z, h2, l2); split_pair(qa0.w, qa1.w, h3, l3);
            dA[0] = make_uint4(h0, l0, h1, l1);
            dA[1] = make_uint4(h2, l2, h3, l3);
            split_pair(qb0.x, qb1.x, h0, l0); split_pair(qb0.y, qb1.y, h1, l1);
            split_pair(qb0.z, qb1.z, h2, l2); split_pair(qb0.w, qb1.w, h3, l3);
            dB[0] = make_uint4(h0, l0, h1, l1);
            dB[1] = make_uint4(h2, l2, h3, l3);
        }
        // prefetch chunk c+2
        if (c < 28) {
            const int nc = c + 2;
            if (nc < 14) {
                const int k0 = nc * 16 + 2 * kp;
                qa0 = ldw0(w0a, k0);  qa1 = ldw0(w0a, k0 + 1);
                qb0 = ldw0(w0b, k0);  qb1 = ldw0(w0b, k0 + 1);
            } else {
                const size_t k0 = (size_t)((nc - 14) * 16 + 2 * kp) * 64;
                qa0 = w1a[k0];  qa1 = w1a[k0 + 64];
                qb0 = w1b[k0];  qb1 = w1b[k0 + 64];
            }
        }
        // MMA chunk c (warp tile 16 x 128)
        {
            const uint2* Bc0 = bB0 + (c & 1) * BBUF;
            const uint2* Bc1 = bB1 + (c & 1) * BBUF;
            uint2 A0[4];
            A0[0] = rA0[0]; A0[1] = rA1[0]; A0[2] = rA0[4]; A0[3] = rA1[4];
            #pragma unroll
            for (int j = 0; j < 16; ++j) {
                const uint2 p0 = Bc0[j * 8];
                const uint2 p1 = Bc1[j * 8];
                float* ac = &acc[j * 4];
                mma_f16(ac, A0[0].x, A0[1].x, A0[2].x, A0[3].x, p0.x, p1.x);
                mma_f16(ac, A0[0].x, A0[1].x, A0[2].x, A0[3].x, p0.y, p1.y);
                mma_f16(ac, A0[0].y, A0[1].y, A0[2].y, A0[3].y, p0.x, p1.x);
            }
        }
        __syncthreads();
        if (c == 13) {
            // H1 writeback: relu(+b0), split to hi/lo, own rows/cols only
            const int r0 = mrow + gid;
            #pragma unroll
            for (int j = 0; j < 16; ++j) {
                float* ac = &acc[j * 4];
                const int gc = nh + j * 8 + tig * 2;
                const int pi = gc >> 1;
                const float h00 = fmaxf(ac[0] + b0S[gc],   0.0f);
                const float h01 = fmaxf(ac[1] + b0S[gc+1], 0.0f);
                const float h10 = fmaxf(ac[2] + b0S[gc],   0.0f);
                const float h11 = fmaxf(ac[3] + b0S[gc+1], 0.0f);
                unsigned h, l;
                split_pair(h00, h01, h, l); X2[r0 * SU2 + pi]       = make_uint2(h, l);
                split_pair(h10, h11, h, l); X2[(r0 + 8) * SU2 + pi] = make_uint2(h, l);
                ac[0] = 0.0f; ac[1] = 0.0f; ac[2] = 0.0f; ac[3] = 0.0f;
            }
            __syncthreads();
            rA0 = rA0base;
            rA1 = rA0base + 8 * SU2;
        } else {
            rA0 += 8; rA1 += 8;
        }
    }

    // ========== Layer 2 (fp32): relu(+b1) then @ w_out[256,4], half partials ==========
    {
        float pA[4] = {0,0,0,0}, pB[4] = {0,0,0,0};
        #pragma unroll
        for (int j = 0; j < 16; ++j) {
            float* ac = &acc[j * 4];
            const int gc = nh + j * 8 + tig * 2;
            const float h00 = fmaxf(ac[0] + b1S[gc],   0.0f);
            const float h01 = fmaxf(ac[1] + b1S[gc+1], 0.0f);
            const float h10 = fmaxf(ac[2] + b1S[gc],   0.0f);
            const float h11 = fmaxf(ac[3] + b1S[gc+1], 0.0f);
            #pragma unroll
            for (int o = 0; o < 4; ++o) {
                const float wv0 = WoutS[gc * 4 + o];
                const float wv1 = WoutS[(gc + 1) * 4 + o];
                pA[o] += h00 * wv0 + h01 * wv1;
                pB[o] += h10 * wv0 + h11 * wv1;
            }
        }
        #pragma unroll
        for (int m = 1; m <= 2; m <<= 1) {
            #pragma unroll
            for (int o = 0; o < 4; ++o) {
                pA[o] += __shfl_xor_sync(0xffffffffu, pA[o], m);
                pB[o] += __shfl_xor_sync(0xffffffffu, pB[o], m);
            }
        }
        if (tig == 0) {
            float* rb = rawS + (warp & 1) * 256;
            #pragma unroll
            for (int o = 0; o < 4; ++o) {
                rb[(mrow + gid)     * 4 + o] = pA[o];
                rb[(mrow + gid + 8) * 4 + o] = pB[o];
            }
        }
    }
    __syncthreads();

    // ---------------- Compositing: one thread (1 ray/block) ----------------
    if (tid == 0) {
        const float dx = rays_d[g*3], dy = rays_d[g*3+1], dz = rays_d[g*3+2];
        const float nd = sqrtf(dx*dx + dy*dy + dz*dz);
        float trans = 1.0f, r0 = 0.0f, r1 = 0.0f, r2 = 0.0f;
        const float ddist = 1.5f / 64.0f;
        for (int n = 0; n < 64; ++n) {
            float raw[4];
            #pragma unroll
            for (int o = 0; o < 4; ++o)
                raw[o] = rawS[n*4+o] + rawS[256 + n*4+o] + boS[o];
            const float sigma = fmaxf(raw[3], 0.0f);
            const float dist  = (n == 63) ? 1e10f : ddist;
            const float alpha = 1.0f - expf(-sigma * dist * nd);
            const float wgt   = alpha * trans;
            trans = trans * (1.0f - alpha + 1e-10f);
            r0 += wgt / (1.0f + expf(-raw[0]));
            r1 += wgt / (1.0f + expf(-raw[1]));
            r2 += wgt / (1.0f + expf(-raw[2]));
        }
        out[g*3+0] = r0; out[g*3+1] = r1; out[g*3+2] = r2;
    }
}

extern "C" void kernel_launch(void* const* d_in, const int* in_sizes, int n_in,
                              void* d_out, int out_size)
{
    const float* rays_o     = (const float*)d_in[0];
    const float* rays_d     = (const float*)d_in[1];
    const float* uv_feat    = (const float*)d_in[2];
    const float* transforms = (const float*)d_in[3];
    const float* w0         = (const float*)d_in[4];
    const float* b0         = (const float*)d_in[5];
    const float* w1         = (const float*)d_in[6];
    const float* b1         = (const float*)d_in[7];
    const float* w_out      = (const float*)d_in[8];
    const float* b_out      = (const float*)d_in[9];
    const int*   uv_idx     = (const int*)d_in[10];
    const int*   vox_idx    = (const int*)d_in[11];
    float* out = (float*)d_out;

    cudaFuncSetAttribute(vh_kernel, cudaFuncAttributeMaxDynamicSharedMemorySize, SMEM_BYTES);

    vh_kernel<<<16384, 256, SMEM_BYTES>>>(rays_o, rays_d, uv_feat, transforms,
                                          w0, b0, w1, b1, w_out, b_out,
                                          uv_idx, vox_idx, out);
}

// round 15
// speedup vs baseline: 1.0012x; 1.0010x over previous
#include <cuda_runtime.h>
#include <cuda_fp16.h>
#include <math.h>

// VoxelHuman fused: embed + gather -> 3xFP16 (m16n8k16) MLP -> compositing.
// R8: block = 1 ray = 64 points, 256 threads (8 warps), smem ~108KB ->
//     2 blocks/SM co-resident (decoupled barriers hide latency).
// Warp tile 16x128. X/H1 pre-split f16 hi/lo. Double-buffered weight staging.

#define SU2 132            // X2 row stride (uint2)
#define BST 268            // B buffer slot stride (uint2)
#define BBUF (8*BST)       // uint2 per B buffer

#define SMEM_BYTES (64*SU2*8 + 2*BBUF*8 + 4096 + 2048 + 768 + 1024 + 1024 + 32)

__device__ __forceinline__ unsigned pack_f16x2(float hi, float lo) {
    unsigned d;
    asm("cvt.rn.f16x2.f32 %0, %1, %2;" : "=r"(d) : "f"(hi), "f"(lo));
    return d;
}

// v0 -> low half (even k), v1 -> high half (odd k)
__device__ __forceinline__ void split_pair(float v0, float v1, unsigned& hi, unsigned& lo) {
    const unsigned h = pack_f16x2(v1, v0);
    const __half2 hh = *reinterpret_cast<const __half2*>(&h);
    const float f0 = __low2float(hh);
    const float f1 = __high2float(hh);
    lo = pack_f16x2(v1 - f1, v0 - f0);
    hi = h;
}

__device__ __forceinline__ void mma_f16(float* c,
                                        unsigned a0, unsigned a1, unsigned a2, unsigned a3,
                                        unsigned b0, unsigned b1) {
    asm("mma.sync.aligned.m16n8k16.row.col.f32.f16.f16.f32 "
        "{%0,%1,%2,%3},{%4,%5,%6,%7},{%8,%9},{%0,%1,%2,%3};\n"
        : "+f"(c[0]), "+f"(c[1]), "+f"(c[2]), "+f"(c[3])
        : "r"(a0), "r"(a1), "r"(a2), "r"(a3), "r"(b0), "r"(b1));
}

// Accurate fp32 sincos (Cody-Waite) — immune to --use_fast_math MUFU reduction.
__device__ __forceinline__ void sincos_acc(float x, float* sp, float* cp) {
    const float j = rintf(x * 0.636619772367581343f);
    const int   q = (int)j;
    float r = fmaf(j, -1.57079637050628662109375f, x);
    r = fmaf(j,  4.37113882867379290e-08f, r);
    r = fmaf(j,  1.71512451000590810e-15f, r);
    const float r2 = r * r;
    float sr = -1.9812813e-4f;
    sr = fmaf(sr, r2,  8.3333226e-3f);
    sr = fmaf(sr, r2, -1.6666667e-1f);
    sr = fmaf(sr * r2, r, r);
    float cr =  2.4372668e-5f;
    cr = fmaf(cr, r2, -1.3887316e-3f);
    cr = fmaf(cr, r2,  4.1666646e-2f);
    cr = fmaf(cr, r2, -5.0000000e-1f);
    cr = fmaf(cr, r2,  1.0f);
    float ss = (q & 1) ? cr : sr;
    float cc = (q & 1) ? sr : cr;
    if (q & 2) ss = -ss;
    if (((q & 2) != 0) != ((q & 1) != 0)) cc = -cc;
    *sp = ss; *cp = cc;
}

__global__ void __launch_bounds__(256, 2)
vh_kernel(const float* __restrict__ rays_o, const float* __restrict__ rays_d,
          const float* __restrict__ uv_feat, const float* __restrict__ transforms,
          const float* __restrict__ w0, const float* __restrict__ b0,
          const float* __restrict__ w1, const float* __restrict__ b1,
          const float* __restrict__ w_out, const float* __restrict__ b_out,
          const int* __restrict__ uv_idx, const int* __restrict__ vox_idx,
          float* __restrict__ out)
{
    extern __shared__ char smraw[];
    uint2* X2    = (uint2*)smraw;               // 64 x SU2 {hi,lo} f16x2 pairs
    uint2* Bb    = X2 + 64 * SU2;               // [2][8][BST] {hi,lo}
    float* WoutS = (float*)(Bb + 2 * BBUF);     // 1024
    float* rawS  = WoutS + 1024;                // 2 x 64 x 4
    float* TfS   = rawS + 512;                  // 192
    float* b0S   = TfS + 192;                   // 256
    float* b1S   = b0S + 256;                   // 256
    float* boS   = b1S + 256;                   // 4 (pad 8)

    const int tid  = threadIdx.x;
    const int lane = tid & 31;
    const int warp = tid >> 5;           // 0..7
    const int gid  = lane >> 2;
    const int tig  = lane & 3;
    const int mrow = (warp >> 1) * 16;   // 16-row group
    const int nh   = (warp & 1) * 128;   // 128-col half

    const int kp   = tid >> 5;           // weight k-pair 0..7
    const int c8   = tid & 31;           // weight col-quad (and +32)

    // stage small constants
    for (int i = tid; i < 192;  i += 256) TfS[i]   = transforms[i];
    for (int i = tid; i < 1024; i += 256) WoutS[i] = w_out[i];
    b0S[tid] = b0[tid];
    b1S[tid] = b1[tid];
    if (tid < 4) boS[tid] = b_out[tid];
    __syncthreads();

    const int g    = blockIdx.x;         // ray index
    const int base = g * 64;             // flat point base

    // hoisted weight cursors (two column quads per thread)
    const float4* w0a = (const float4*)w0 + c8;
    const float4* w0b = w0a + 32;
    const float4* w1a = (const float4*)w1 + c8;
    const float4* w1b = w1a + 32;
    // layer-0 smem k layout: [0..62]=w0 rows 0..62, 63=zero, [64..211]=w0 rows 63..210
    auto ldw0 = [](const float4* cur, int k) -> float4 {
        if (k < 63)  return cur[(size_t)k * 64];
        if (k >= 64 && k < 212) return cur[(size_t)(k - 1) * 64];
        return make_float4(0.f, 0.f, 0.f, 0.f);
    };

    float4 qa0, qa1, qb0, qb1;   // prefetched next chunk (rows 2kp, 2kp+1; quads c8, c8+32)
    qa0 = ldw0(w0a, 2 * kp);  qa1 = ldw0(w0a, 2 * kp + 1);
    qb0 = ldw0(w0b, 2 * kp);  qb1 = ldw0(w0b, 2 * kp + 1);

    // ---------------- Phase 1: build X (pre-split hi/lo pairs) ----------------
    if (tid < 64) {
        const int p = tid;                 // sample index 0..63
        const float z = 0.5f + (float)p * (1.5f / 64.0f);
        const float px = rays_o[g*3+0] + rays_d[g*3+0] * z;
        const float py = rays_o[g*3+1] + rays_d[g*3+1] * z;
        const float pz = rays_o[g*3+2] + rays_d[g*3+2] * z;
        const int vox = vox_idx[base + p];
        const float* T = TfS + vox * 12;
        float xv[64];
        xv[0] = T[0]*px + T[1]*py + T[2]*pz  + T[3];
        xv[1] = T[4]*px + T[5]*py + T[6]*pz  + T[7];
        xv[2] = T[8]*px + T[9]*py + T[10]*pz + T[11];
        float f = 1.0f;
        #pragma unroll
        for (int k = 0; k < 10; ++k) {
            float s, c;
            sincos_acc(xv[0] * f, &s, &c); xv[3+6*k+0] = s; xv[3+6*k+3] = c;
            sincos_acc(xv[1] * f, &s, &c); xv[3+6*k+1] = s; xv[3+6*k+4] = c;
            sincos_acc(xv[2] * f, &s, &c); xv[3+6*k+2] = s; xv[3+6*k+5] = c;
            f *= 2.0f;
        }
        xv[63] = 0.0f;
        uint2* xr = X2 + p * SU2;
        #pragma unroll
        for (int q = 0; q < 32; ++q) {
            unsigned h, l;
            split_pair(xv[2*q], xv[2*q+1], h, l);
            xr[q] = make_uint2(h, l);
        }
        #pragma unroll
        for (int q = 106; q < 112; ++q) xr[q] = make_uint2(0u, 0u);
    } else {
        // 192 threads gather uv_feat (148 ch): 3 threads per point
        const int t3  = tid - 64;
        const int p   = t3 & 63;
        const int sub = t3 >> 6;        // 0..2
        const int bi  = g >> 13;        // batch index (8192 rays per batch)
        const int uvi = uv_idx[base + p];
        const float4* src =
            (const float4*)(uv_feat + ((size_t)bi * 65536 + (size_t)uvi) * 148);
        uint2* xr = X2 + p * SU2;
        for (int q = sub; q < 37; q += 3) {
            const float4 v = src[q];
            unsigned h0, l0, h1, l1;
            split_pair(v.x, v.y, h0, l0);
            split_pair(v.z, v.w, h1, l1);
            *(uint4*)(xr + 32 + 2 * q) = make_uint4(h0, l0, h1, l1);
        }
    }

    // stage chunk 0 into buf 0
    uint4* stgA = (uint4*)(Bb + kp * BST + c8 * 4);
    uint4* stgB = (uint4*)(Bb + kp * BST + (c8 + 32) * 4);
    {
        unsigned h0,l0,h1,l1,h2,l2,h3,l3;
        split_pair(qa0.x, qa1.x, h0, l0); split_pair(qa0.y, qa1.y, h1, l1);
        split_pair(qa0.z, qa1.z, h2, l2); split_pair(qa0.w, qa1.w, h3, l3);
        stgA[0] = make_uint4(h0, l0, h1, l1);
        stgA[1] = make_uint4(h2, l2, h3, l3);
        split_pair(qb0.x, qb1.x, h0, l0); split_pair(qb0.y, qb1.y, h1, l1);
        split_pair(qb0.z, qb1.z, h2, l2); split_pair(qb0.w, qb1.w, h3, l3);
        stgB[0] = make_uint4(h0, l0, h1, l1);
        stgB[1] = make_uint4(h2, l2, h3, l3);
    }
    // prefetch chunk 1
    qa0 = ldw0(w0a, 16 + 2 * kp);  qa1 = ldw0(w0a, 16 + 2 * kp + 1);
    qb0 = ldw0(w0b, 16 + 2 * kp);  qb1 = ldw0(w0b, 16 + 2 * kp + 1);

    float acc[64];
    #pragma unroll
    for (int i = 0; i < 64; ++i) acc[i] = 0.0f;

    // hoisted A-row cursors (advance +8 per chunk, reset at layer switch)
    const uint2* rA0base = X2 + (mrow + gid) * SU2 + tig;
    const uint2* rA0 = rA0base;
    const uint2* rA1 = rA0base + 8 * SU2;
    // hoisted B-read cursors
    const uint2* bB0 = Bb + tig * BST + nh + gid;
    const uint2* bB1 = Bb + (tig + 4) * BST + nh + gid;

    __syncthreads();

    // ================= Unified chunk loop: 14 (layer0) + 16 (layer1) =================
    #pragma unroll 2
    for (int c = 0; c < 30; ++c) {
        // stage prefetched chunk c+1 into the other buffer
        if (c < 29) {
            unsigned h0,l0,h1,l1,h2,l2,h3,l3;
            uint4* dA = stgA + ((c + 1) & 1) * (BBUF / 2);
            uint4* dB = stgB + ((c + 1) & 1) * (BBUF / 2);
            split_pair(qa0.x, qa1.x, h0, l0); split_pair(qa0.y, qa1.y, h1, l1);
            split_pair(qa0.z, qa1.z, h2, l2); split_pair(qa0.w, qa1.w, h3, l3);
            dA[0] = make_uint4(h0, l0, h1, l1);
            dA[1] = make_uint4(h2, l2, h3, l3);
            split_pair(qb0.x, qb1.x, h0, l0); split_pair(qb0.y, qb1.y, h1, l1);
            split_pair(qb0.z, qb1.z, h2, l2); split_pair(qb0.w, qb1.w, h3, l3);
            dB[0] = make_uint4(h0, l0, h1, l1);
            dB[1] = make_uint4(h2, l2, h3, l3);
        }
        // prefetch chunk c+2
        if (c < 28) {
            const int nc = c + 2;
            if (nc < 14) {
                const int k0 = nc * 16 + 2 * kp;
                qa0 = ldw0(w0a, k0);  qa1 = ldw0(w0a, k0 + 1);
                qb0 = ldw0(w0b, k0);  qb1 = ldw0(w0b, k0 + 1);
            } else {
                const size_t k0 = (size_t)((nc - 14) * 16 + 2 * kp) * 64;
                qa0 = w1a[k0];  qa1 = w1a[k0 + 64];
                qb0 = w1b[k0];  qb1 = w1b[k0 + 64];
            }
        }
        // MMA chunk c (warp tile 16 x 128)
        {
            const uint2* Bc0 = bB0 + (c & 1) * BBUF;
            const uint2* Bc1 = bB1 + (c & 1) * BBUF;
            uint2 A0[4];
            A0[0] = rA0[0]; A0[1] = rA1[0]; A0[2] = rA0[4]; A0[3] = rA1[4];
            #pragma unroll
            for (int j = 0; j < 16; ++j) {
                const uint2 p0 = Bc0[j * 8];
                const uint2 p1 = Bc1[j * 8];
                float* ac = &acc[j * 4];
                mma_f16(ac, A0[0].x, A0[1].x, A0[2].x, A0[3].x, p0.x, p1.x);
                mma_f16(ac, A0[0].x, A0[1].x, A0[2].x, A0[3].x, p0.y, p1.y);
                mma_f16(ac, A0[0].y, A0[1].y, A0[2].y, A0[3].y, p0.x, p1.x);
            }
        }
        __syncthreads();
        if (c == 13) {
            // H1 writeback: relu(+b0), split to hi/lo, own rows/cols only
            const int r0 = mrow + gid;
            #pragma unroll
            for (int j = 0; j < 16; ++j) {
                float* ac = &acc[j * 4];
                const int gc = nh + j * 8 + tig * 2;
                const int pi = gc >> 1;
                const float h00 = fmaxf(ac[0] + b0S[gc],   0.0f);
                const float h01 = fmaxf(ac[1] + b0S[gc+1], 0.0f);
                const float h10 = fmaxf(ac[2] + b0S[gc],   0.0f);
                const float h11 = fmaxf(ac[3] + b0S[gc+1], 0.0f);
                unsigned h, l;
                split_pair(h00, h01, h, l); X2[r0 * SU2 + pi]       = make_uint2(h, l);
                split_pair(h10, h11, h, l); X2[(r0 + 8) * SU2 + pi] = make_uint2(h, l);
                ac[0] = 0.0f; ac[1] = 0.0f; ac[2] = 0.0f; ac[3] = 0.0f;
            }
            __syncthreads();
            rA0 = rA0base;
            rA1 = rA0base + 8 * SU2;
        } else {
            rA0 += 8; rA1 += 8;
        }
    }

    // ========== Layer 2 (fp32): relu(+b1) then @ w_out[256,4], half partials ==========
    {
        float pA[4] = {0,0,0,0}, pB[4] = {0,0,0,0};
        #pragma unroll
        for (int j = 0; j < 16; ++j) {
            float* ac = &acc[j * 4];
            const int gc = nh + j * 8 + tig * 2;
            const float h00 = fmaxf(ac[0] + b1S[gc],   0.0f);
            const float h01 = fmaxf(ac[1] + b1S[gc+1], 0.0f);
            const float h10 = fmaxf(ac[2] + b1S[gc],   0.0f);
            const float h11 = fmaxf(ac[3] + b1S[gc+1], 0.0f);
            #pragma unroll
            for (int o = 0; o < 4; ++o) {
                const float wv0 = WoutS[gc * 4 + o];
                const float wv1 = WoutS[(gc + 1) * 4 + o];
                pA[o] += h00 * wv0 + h01 * wv1;
                pB[o] += h10 * wv0 + h11 * wv1;
            }
        }
        #pragma unroll
        for (int m = 1; m <= 2; m <<= 1) {
            #pragma unroll
            for (int o = 0; o < 4; ++o) {
                pA[o] += __shfl_xor_sync(0xffffffffu, pA[o], m);
                pB[o] += __shfl_xor_sync(0xffffffffu, pB[o], m);
            }
        }
        if (tig == 0) {
            float* rb = rawS + (warp & 1) * 256;
            #pragma unroll
            for (int o = 0; o < 4; ++o) {
                rb[(mrow + gid)     * 4 + o] = pA[o];
                rb[(mrow + gid + 8) * 4 + o] = pB[o];
            }
        }
    }
    __syncthreads();

    // ---------------- Compositing: one thread (1 ray/block) ----------------
    if (tid == 0) {
        const float dx = rays_d[g*3], dy = rays_d[g*3+1], dz = rays_d[g*3+2];
        const float nd = sqrtf(dx*dx + dy*dy + dz*dz);
        float trans = 1.0f, r0 = 0.0f, r1 = 0.0f, r2 = 0.0f;
        const float ddist = 1.5f / 64.0f;
        for (int n = 0; n < 64; ++n) {
            float raw[4];
            #pragma unroll
            for (int o = 0; o < 4; ++o)
                raw[o] = rawS[n*4+o] + rawS[256 + n*4+o] + boS[o];
            const float sigma = fmaxf(raw[3], 0.0f);
            const float dist  = (n == 63) ? 1e10f : ddist;
            const float alpha = 1.0f - expf(-sigma * dist * nd);
            const float wgt   = alpha * trans;
            trans = trans * (1.0f - alpha + 1e-10f);
            r0 += wgt / (1.0f + expf(-raw[0]));
            r1 += wgt / (1.0f + expf(-raw[1]));
            r2 += wgt / (1.0f + expf(-raw[2]));
        }
        out[g*3+0] = r0; out[g*3+1] = r1; out[g*3+2] = r2;
    }
}

extern "C" void kernel_launch(void* const* d_in, const int* in_sizes, int n_in,
                              void* d_out, int out_size)
{
    const float* rays_o     = (const float*)d_in[0];
    const float* rays_d     = (const float*)d_in[1];
    const float* uv_feat    = (const float*)d_in[2];
    const float* transforms = (const float*)d_in[3];
    const float* w0         = (const float*)d_in[4];
    const float* b0         = (const float*)d_in[5];
    const float* w1         = (const float*)d_in[6];
    const float* b1         = (const float*)d_in[7];
    const float* w_out      = (const float*)d_in[8];
    const float* b_out      = (const float*)d_in[9];
    const int*   uv_idx     = (const int*)d_in[10];
    const int*   vox_idx    = (const int*)d_in[11];
    float* out = (float*)d_out;

    cudaFuncSetAttribute(vh_kernel, cudaFuncAttributeMaxDynamicSharedMemorySize, SMEM_BYTES);

    vh_kernel<<<16384, 256, SMEM_BYTES>>>(rays_o, rays_d, uv_feat, transforms,
                                          w0, b0, w1, b1, w_out, b_out,
                                          uv_idx, vox_idx, out);
}

// round 16
// speedup vs baseline: 1.0015x; 1.0003x over previous
#include <cuda_runtime.h>
#include <cuda_fp16.h>
#include <math.h>

// VoxelHuman fused: embed + gather -> 3xFP16 (m16n8k16) MLP -> compositing.
// R8: block = 1 ray = 64 points, 256 threads (8 warps), smem ~108KB ->
//     2 blocks/SM co-resident (decoupled barriers hide latency).
// Warp tile 16x128. X/H1 pre-split f16 hi/lo. Double-buffered weight staging.

#define SU2 132            // X2 row stride (uint2)
#define BST 268            // B buffer slot stride (uint2)
#define BBUF (8*BST)       // uint2 per B buffer

#define SMEM_BYTES (64*SU2*8 + 2*BBUF*8 + 4096 + 2048 + 768 + 1024 + 1024 + 32)

__device__ __forceinline__ unsigned pack_f16x2(float hi, float lo) {
    unsigned d;
    asm("cvt.rn.f16x2.f32 %0, %1, %2;" : "=r"(d) : "f"(hi), "f"(lo));
    return d;
}

// v0 -> low half (even k), v1 -> high half (odd k)
__device__ __forceinline__ void split_pair(float v0, float v1, unsigned& hi, unsigned& lo) {
    const unsigned h = pack_f16x2(v1, v0);
    const __half2 hh = *reinterpret_cast<const __half2*>(&h);
    const float f0 = __low2float(hh);
    const float f1 = __high2float(hh);
    lo = pack_f16x2(v1 - f1, v0 - f0);
    hi = h;
}

__device__ __forceinline__ void mma_f16(float* c,
                                        unsigned a0, unsigned a1, unsigned a2, unsigned a3,
                                        unsigned b0, unsigned b1) {
    asm("mma.sync.aligned.m16n8k16.row.col.f32.f16.f16.f32 "
        "{%0,%1,%2,%3},{%4,%5,%6,%7},{%8,%9},{%0,%1,%2,%3};\n"
        : "+f"(c[0]), "+f"(c[1]), "+f"(c[2]), "+f"(c[3])
        : "r"(a0), "r"(a1), "r"(a2), "r"(a3), "r"(b0), "r"(b1));
}

// Accurate fp32 sincos (Cody-Waite) — immune to --use_fast_math MUFU reduction.
__device__ __forceinline__ void sincos_acc(float x, float* sp, float* cp) {
    const float j = rintf(x * 0.636619772367581343f);
    const int   q = (int)j;
    float r = fmaf(j, -1.57079637050628662109375f, x);
    r = fmaf(j,  4.37113882867379290e-08f, r);
    r = fmaf(j,  1.71512451000590810e-15f, r);
    const float r2 = r * r;
    float sr = -1.9812813e-4f;
    sr = fmaf(sr, r2,  8.3333226e-3f);
    sr = fmaf(sr, r2, -1.6666667e-1f);
    sr = fmaf(sr * r2, r, r);
    float cr =  2.4372668e-5f;
    cr = fmaf(cr, r2, -1.3887316e-3f);
    cr = fmaf(cr, r2,  4.1666646e-2f);
    cr = fmaf(cr, r2, -5.0000000e-1f);
    cr = fmaf(cr, r2,  1.0f);
    float ss = (q & 1) ? cr : sr;
    float cc = (q & 1) ? sr : cr;
    if (q & 2) ss = -ss;
    if (((q & 2) != 0) != ((q & 1) != 0)) cc = -cc;
    *sp = ss; *cp = cc;
}

__global__ void __launch_bounds__(256, 2)
vh_kernel(const float* __restrict__ rays_o, const float* __restrict__ rays_d,
          const float* __restrict__ uv_feat, const float* __restrict__ transforms,
          const float* __restrict__ w0, const float* __restrict__ b0,
          const float* __restrict__ w1, const float* __restrict__ b1,
          const float* __restrict__ w_out, const float* __restrict__ b_out,
          const int* __restrict__ uv_idx, const int* __restrict__ vox_idx,
          float* __restrict__ out)
{
    extern __shared__ char smraw[];
    uint2* X2    = (uint2*)smraw;               // 64 x SU2 {hi,lo} f16x2 pairs
    uint2* Bb    = X2 + 64 * SU2;               // [2][8][BST] {hi,lo}
    float* WoutS = (float*)(Bb + 2 * BBUF);     // 1024
    float* rawS  = WoutS + 1024;                // 2 x 64 x 4
    float* TfS   = rawS + 512;                  // 192
    float* b0S   = TfS + 192;                   // 256
    float* b1S   = b0S + 256;                   // 256
    float* boS   = b1S + 256;                   // 4 (pad 8)

    const int tid  = threadIdx.x;
    const int lane = tid & 31;
    const int warp = tid >> 5;           // 0..7
    const int gid  = lane >> 2;
    const int tig  = lane & 3;
    const int mrow = (warp >> 1) * 16;   // 16-row group
    const int nh   = (warp & 1) * 128;   // 128-col half

    const int kp   = tid >> 5;           // weight k-pair 0..7
    const int c8   = tid & 31;           // weight col-quad (and +32)

    // stage small constants
    for (int i = tid; i < 192;  i += 256) TfS[i]   = transforms[i];
    for (int i = tid; i < 1024; i += 256) WoutS[i] = w_out[i];
    b0S[tid] = b0[tid];
    b1S[tid] = b1[tid];
    if (tid < 4) boS[tid] = b_out[tid];
    __syncthreads();

    const int g    = blockIdx.x;         // ray index
    const int base = g * 64;             // flat point base

    // hoisted weight cursors (two column quads per thread)
    const float4* w0a = (const float4*)w0 + c8;
    const float4* w0b = w0a + 32;
    const float4* w1a = (const float4*)w1 + c8;
    const float4* w1b = w1a + 32;
    // layer-0 smem k layout: [0..62]=w0 rows 0..62, 63=zero, [64..211]=w0 rows 63..210
    auto ldw0 = [](const float4* cur, int k) -> float4 {
        if (k < 63)  return cur[(size_t)k * 64];
        if (k >= 64 && k < 212) return cur[(size_t)(k - 1) * 64];
        return make_float4(0.f, 0.f, 0.f, 0.f);
    };

    float4 qa0, qa1, qb0, qb1;   // prefetched next chunk (rows 2kp, 2kp+1; quads c8, c8+32)
    qa0 = ldw0(w0a, 2 * kp);  qa1 = ldw0(w0a, 2 * kp + 1);
    qb0 = ldw0(w0b, 2 * kp);  qb1 = ldw0(w0b, 2 * kp + 1);

    // ---------------- Phase 1: build X (pre-split hi/lo pairs) ----------------
    if (tid < 64) {
        const int p = tid;                 // sample index 0..63
        const float z = 0.5f + (float)p * (1.5f / 64.0f);
        const float px = rays_o[g*3+0] + rays_d[g*3+0] * z;
        const float py = rays_o[g*3+1] + rays_d[g*3+1] * z;
        const float pz = rays_o[g*3+2] + rays_d[g*3+2] * z;
        const int vox = vox_idx[base + p];
        const float* T = TfS + vox * 12;
        float xv[64];
        xv[0] = T[0]*px + T[1]*py + T[2]*pz  + T[3];
        xv[1] = T[4]*px + T[5]*py + T[6]*pz  + T[7];
        xv[2] = T[8]*px + T[9]*py + T[10]*pz + T[11];
        float f = 1.0f;
        #pragma unroll
        for (int k = 0; k < 10; ++k) {
            float s, c;
            sincos_acc(xv[0] * f, &s, &c); xv[3+6*k+0] = s; xv[3+6*k+3] = c;
            sincos_acc(xv[1] * f, &s, &c); xv[3+6*k+1] = s; xv[3+6*k+4] = c;
            sincos_acc(xv[2] * f, &s, &c); xv[3+6*k+2] = s; xv[3+6*k+5] = c;
            f *= 2.0f;
        }
        xv[63] = 0.0f;
        uint2* xr = X2 + p * SU2;
        #pragma unroll
        for (int q = 0; q < 32; ++q) {
            unsigned h, l;
            split_pair(xv[2*q], xv[2*q+1], h, l);
            xr[q] = make_uint2(h, l);
        }
        #pragma unroll
        for (int q = 106; q < 112; ++q) xr[q] = make_uint2(0u, 0u);
    } else {
        // 192 threads gather uv_feat (148 ch): 3 threads per point
        const int t3  = tid - 64;
        const int p   = t3 & 63;
        const int sub = t3 >> 6;        // 0..2
        const int bi  = g >> 13;        // batch index (8192 rays per batch)
        const int uvi = uv_idx[base + p];
        const float4* src =
            (const float4*)(uv_feat + ((size_t)bi * 65536 + (size_t)uvi) * 148);
        uint2* xr = X2 + p * SU2;
        for (int q = sub; q < 37; q += 3) {
            const float4 v = src[q];
            unsigned h0, l0, h1, l1;
            split_pair(v.x, v.y, h0, l0);
            split_pair(v.z, v.w, h1, l1);
            *(uint4*)(xr + 32 + 2 * q) = make_uint4(h0, l0, h1, l1);
        }
    }

    // stage chunk 0 into buf 0
    uint4* stgA = (uint4*)(Bb + kp * BST + c8 * 4);
    uint4* stgB = (uint4*)(Bb + kp * BST + (c8 + 32) * 4);
    {
        unsigned h0,l0,h1,l1,h2,l2,h3,l3;
        split_pair(qa0.x, qa1.x, h0, l0); split_pair(qa0.y, qa1.y, h1, l1);
        split_pair(qa0.z, qa1.z, h2, l2); split_pair(qa0.w, qa1.w, h3, l3);
        stgA[0] = make_uint4(h0, l0, h1, l1);
        stgA[1] = make_uint4(h2, l2, h3, l3);
        split_pair(qb0.x, qb1.x, h0, l0); split_pair(qb0.y, qb1.y, h1, l1);
        split_pair(qb0.z, qb1.z, h2, l2); split_pair(qb0.w, qb1.w, h3, l3);
        stgB[0] = make_uint4(h0, l0, h1, l1);
        stgB[1] = make_uint4(h2, l2, h3, l3);
    }
    // prefetch chunk 1
    qa0 = ldw0(w0a, 16 + 2 * kp);  qa1 = ldw0(w0a, 16 + 2 * kp + 1);
    qb0 = ldw0(w0b, 16 + 2 * kp);  qb1 = ldw0(w0b, 16 + 2 * kp + 1);

    float acc[64];
    #pragma unroll
    for (int i = 0; i < 64; ++i) acc[i] = 0.0f;

    // hoisted A-row cursors (advance +8 per chunk, reset at layer switch)
    const uint2* rA0base = X2 + (mrow + gid) * SU2 + tig;
    const uint2* rA0 = rA0base;
    const uint2* rA1 = rA0base + 8 * SU2;
    // hoisted B-read cursors
    const uint2* bB0 = Bb + tig * BST + nh + gid;
    const uint2* bB1 = Bb + (tig + 4) * BST + nh + gid;

    __syncthreads();

    // ================= Unified chunk loop: 14 (layer0) + 16 (layer1) =================
    #pragma unroll 2
    for (int c = 0; c < 30; ++c) {
        // stage prefetched chunk c+1 into the other buffer
        if (c < 29) {
            unsigned h0,l0,h1,l1,h2,l2,h3,l3;
            uint4* dA = stgA + ((c + 1) & 1) * (BBUF / 2);
            uint4* dB = stgB + ((c + 1) & 1) * (BBUF / 2);
            split_pair(qa0.x, qa1.x, h0, l0); split_pair(qa0.y, qa1.y, h1, l1);
            split_pair(qa0.z, qa1.z, h2, l2); split_pair(qa0.w, qa1.w, h3, l3);
            dA[0] = make_uint4(h0, l0, h1, l1);
            dA[1] = make_uint4(h2, l2, h3, l3);
            split_pair(qb0.x, qb1.x, h0, l0); split_pair(qb0.y, qb1.y, h1, l1);
            split_pair(qb0.z, qb1.z, h2, l2); split_pair(qb0.w, qb1.w, h3, l3);
            dB[0] = make_uint4(h0, l0, h1, l1);
            dB[1] = make_uint4(h2, l2, h3, l3);
        }
        // prefetch chunk c+2
        if (c < 28) {
            const int nc = c + 2;
            if (nc < 14) {
                const int k0 = nc * 16 + 2 * kp;
                qa0 = ldw0(w0a, k0);  qa1 = ldw0(w0a, k0 + 1);
                qb0 = ldw0(w0b, k0);  qb1 = ldw0(w0b, k0 + 1);
            } else {
                const size_t k0 = (size_t)((nc - 14) * 16 + 2 * kp) * 64;
                qa0 = w1a[k0];  qa1 = w1a[k0 + 64];
                qb0 = w1b[k0];  qb1 = w1b[k0 + 64];
            }
        }
        // MMA chunk c (warp tile 16 x 128)
        {
            const uint2* Bc0 = bB0 + (c & 1) * BBUF;
            const uint2* Bc1 = bB1 + (c & 1) * BBUF;
            uint2 A0[4];
            A0[0] = rA0[0]; A0[1] = rA1[0]; A0[2] = rA0[4]; A0[3] = rA1[4];
            #pragma unroll
            for (int j = 0; j < 16; ++j) {
                const uint2 p0 = Bc0[j * 8];
                const uint2 p1 = Bc1[j * 8];
                float* ac = &acc[j * 4];
                mma_f16(ac, A0[0].x, A0[1].x, A0[2].x, A0[3].x, p0.x, p1.x);
                mma_f16(ac, A0[0].x, A0[1].x, A0[2].x, A0[3].x, p0.y, p1.y);
                mma_f16(ac, A0[0].y, A0[1].y, A0[2].y, A0[3].y, p0.x, p1.x);
            }
        }
        __syncthreads();
        if (c == 13) {
            // H1 writeback: relu(+b0), split to hi/lo, own rows/cols only
            const int r0 = mrow + gid;
            #pragma unroll
            for (int j = 0; j < 16; ++j) {
                float* ac = &acc[j * 4];
                const int gc = nh + j * 8 + tig * 2;
                const int pi = gc >> 1;
                const float h00 = fmaxf(ac[0] + b0S[gc],   0.0f);
                const float h01 = fmaxf(ac[1] + b0S[gc+1], 0.0f);
                const float h10 = fmaxf(ac[2] + b0S[gc],   0.0f);
                const float h11 = fmaxf(ac[3] + b0S[gc+1], 0.0f);
                unsigned h, l;
                split_pair(h00, h01, h, l); X2[r0 * SU2 + pi]       = make_uint2(h, l);
                split_pair(h10, h11, h, l); X2[(r0 + 8) * SU2 + pi] = make_uint2(h, l);
                ac[0] = 0.0f; ac[1] = 0.0f; ac[2] = 0.0f; ac[3] = 0.0f;
            }
            __syncthreads();
            rA0 = rA0base;
            rA1 = rA0base + 8 * SU2;
        } else {
            rA0 += 8; rA1 += 8;
        }
    }

    // ========== Layer 2 (fp32): relu(+b1) then @ w_out[256,4], half partials ==========
    {
        float pA[4] = {0,0,0,0}, pB[4] = {0,0,0,0};
        #pragma unroll
        for (int j = 0; j < 16; ++j) {
            float* ac = &acc[j * 4];
            const int gc = nh + j * 8 + tig * 2;
            const float h00 = fmaxf(ac[0] + b1S[gc],   0.0f);
            const float h01 = fmaxf(ac[1] + b1S[gc+1], 0.0f);
            const float h10 = fmaxf(ac[2] + b1S[gc],   0.0f);
            const float h11 = fmaxf(ac[3] + b1S[gc+1], 0.0f);
            #pragma unroll
            for (int o = 0; o < 4; ++o) {
                const float wv0 = WoutS[gc * 4 + o];
                const float wv1 = WoutS[(gc + 1) * 4 + o];
                pA[o] += h00 * wv0 + h01 * wv1;
                pB[o] += h10 * wv0 + h11 * wv1;
            }
        }
        #pragma unroll
        for (int m = 1; m <= 2; m <<= 1) {
            #pragma unroll
            for (int o = 0; o < 4; ++o) {
                pA[o] += __shfl_xor_sync(0xffffffffu, pA[o], m);
                pB[o] += __shfl_xor_sync(0xffffffffu, pB[o], m);
            }
        }
        if (tig == 0) {
            float* rb = rawS + (warp & 1) * 256;
            #pragma unroll
            for (int o = 0; o < 4; ++o) {
                rb[(mrow + gid)     * 4 + o] = pA[o];
                rb[(mrow + gid + 8) * 4 + o] = pB[o];
            }
        }
    }
    __syncthreads();

    // ---------------- Compositing: one thread (1 ray/block) ----------------
    if (tid == 0) {
        const float dx = rays_d[g*3], dy = rays_d[g*3+1], dz = rays_d[g*3+2];
        const float nd = sqrtf(dx*dx + dy*dy + dz*dz);
        float trans = 1.0f, r0 = 0.0f, r1 = 0.0f, r2 = 0.0f;
        const float ddist = 1.5f / 64.0f;
        for (int n = 0; n < 64; ++n) {
            float raw[4];
            #pragma unroll
            for (int o = 0; o < 4; ++o)
                raw[o] = rawS[n*4+o] + rawS[256 + n*4+o] + boS[o];
            const float sigma = fmaxf(raw[3], 0.0f);
            const float dist  = (n == 63) ? 1e10f : ddist;
            const float alpha = 1.0f - expf(-sigma * dist * nd);
            const float wgt   = alpha * trans;
            trans = trans * (1.0f - alpha + 1e-10f);
            r0 += wgt / (1.0f + expf(-raw[0]));
            r1 += wgt / (1.0f + expf(-raw[1]));
            r2 += wgt / (1.0f + expf(-raw[2]));
        }
        out[g*3+0] = r0; out[g*3+1] = r1; out[g*3+2] = r2;
    }
}

extern "C" void kernel_launch(void* const* d_in, const int* in_sizes, int n_in,
                              void* d_out, int out_size)
{
    const float* rays_o     = (const float*)d_in[0];
    const float* rays_d     = (const float*)d_in[1];
    const float* uv_feat    = (const float*)d_in[2];
    const float* transforms = (const float*)d_in[3];
    const float* w0         = (const float*)d_in[4];
    const float* b0         = (const float*)d_in[5];
    const float* w1         = (const float*)d_in[6];
    const float* b1         = (const float*)d_in[7];
    const float* w_out      = (const float*)d_in[8];
    const float* b_out      = (const float*)d_in[9];
    const int*   uv_idx     = (const int*)d_in[10];
    const int*   vox_idx    = (const int*)d_in[11];
    float* out = (float*)d_out;

    cudaFuncSetAttribute(vh_kernel, cudaFuncAttributeMaxDynamicSharedMemorySize, SMEM_BYTES);

    vh_kernel<<<16384, 256, SMEM_BYTES>>>(rays_o, rays_d, uv_feat, transforms,
                                          w0, b0, w1, b1, w_out, b_out,
                                          uv_idx, vox_idx, out);
}